// round 5
// baseline (speedup 1.0000x reference)
#include <cuda_runtime.h>
#include <math.h>

// ISTFT: BC=64; F=513; T=1024; n_fft=1024; hop=256.
// One warp = one frame: irfft(1024) via half-size 512-pt complex inverse FFT,
// decomposed 512 = 2*16*16, all exchanges via warp shuffles (no smem FFT traffic).
// Smem used only for: coalesced load staging (pack), overlap-add accumulator, twiddle table.

#define FPC 8                 // frames per CTA (one per warp, 256 threads)
#define ACC_F2 1408           // 128*7 + 512
#define ACC_FLOATS 2816
#define INT_LO_F 768          // exclusively-owned interior of acc (floats)
#define INT_HI_F 2048
#define OUT_PER_BC 262400
#define BUFS 516              // staging row stride (f2), bank-spread

__device__ __forceinline__ float2 cmul(float2 a, float2 b) {
    return make_float2(a.x * b.x - a.y * b.y, a.x * b.y + a.y * b.x);
}
__device__ __forceinline__ float2 cadd(float2 a, float2 b) { return make_float2(a.x + b.x, a.y + b.y); }
__device__ __forceinline__ float2 csub(float2 a, float2 b) { return make_float2(a.x - b.x, a.y - b.y); }
__device__ __forceinline__ float2 cmuli(float2 a) { return make_float2(-a.y, a.x); }  // * i

// inverse radix-4: y[u] = sum_t x[t] * i^{ut}
__device__ __forceinline__ void r4i(float2 a, float2 b, float2 c, float2 d, float2 y[4]) {
    float2 t0 = cadd(a, c), t1 = csub(a, c);
    float2 t2 = cadd(b, d), t3 = cmuli(csub(b, d));
    y[0] = cadd(t0, t2); y[1] = cadd(t1, t3); y[2] = csub(t0, t2); y[3] = csub(t1, t3);
}

// inverse radix-16 in registers: y[u] = sum_t x[t] e^{+2 pi i u t/16}
__device__ __forceinline__ void bfly16(const float2 x[16], float2 y[16]) {
    const float c1 = 0.92387953251128675f, s1 = 0.38268343236508977f, r2 = 0.70710678118654752f;
    const float2 W1 = make_float2(c1, s1), W2 = make_float2(r2, r2), W3 = make_float2(s1, c1);
    const float2 W6 = make_float2(-r2, r2), W9 = make_float2(-c1, -s1);
    float2 A0[4], A1[4], A2[4], A3[4], t[4];
    r4i(x[0], x[4], x[8],  x[12], A0);
    r4i(x[1], x[5], x[9],  x[13], A1);
    r4i(x[2], x[6], x[10], x[14], A2);
    r4i(x[3], x[7], x[11], x[15], A3);
    A1[1] = cmul(A1[1], W1); A1[2] = cmul(A1[2], W2); A1[3] = cmul(A1[3], W3);
    A2[1] = cmul(A2[1], W2); A2[2] = cmuli(A2[2]);    A2[3] = cmul(A2[3], W6);
    A3[1] = cmul(A3[1], W3); A3[2] = cmul(A3[2], W6); A3[3] = cmul(A3[3], W9);
    r4i(A0[0], A1[0], A2[0], A3[0], t); y[0] = t[0]; y[4] = t[1]; y[8]  = t[2]; y[12] = t[3];
    r4i(A0[1], A1[1], A2[1], A3[1], t); y[1] = t[0]; y[5] = t[1]; y[9]  = t[2]; y[13] = t[3];
    r4i(A0[2], A1[2], A2[2], A3[2], t); y[2] = t[0]; y[6] = t[1]; y[10] = t[2]; y[14] = t[3];
    r4i(A0[3], A1[3], A2[3], A3[3], t); y[3] = t[0]; y[7] = t[1]; y[11] = t[2]; y[15] = t[3];
}

__global__ void __launch_bounds__(256, 2) istft_kernel(const float2* __restrict__ in,
                                                       float* __restrict__ out) {
    __shared__ float2 buf[FPC * BUFS];   // 4128 f2: packed-spectrum staging
    __shared__ float2 acc2[ACC_F2];      // overlap-add accumulator
    __shared__ float2 tw1024[513];       // e^{+2 pi i k/1024}

    const int tid = threadIdx.x;
    const int l = tid & 31;              // lane
    const int jf = tid >> 5;             // frame (warp) index, 0..7
    const int bc = blockIdx.y;
    const int tbase = blockIdx.x * FPC;

    // ---- tables + zero edge chunks of acc (regions 0..2 and 8..10) ----
    for (int i = tid; i < 513; i += 256) {
        float s, c;
        __sincosf(6.283185307179586f * (float)i / 1024.0f, &s, &c);
        tw1024[i] = make_float2(c, s);
    }
    for (int i = tid; i < 384; i += 256) {
        acc2[i] = make_float2(0.f, 0.f);
        acc2[1024 + i] = make_float2(0.f, 0.f);
    }
    __syncthreads();

    // ---- pack: C2R -> half-size C2C, coalesced gmem reads, each bin once ----
    {
        const float SC = 0.015625f;   // 1/2 pack * 1/512 ifft * sqrt(1024) * 1/2 coeff
        const float2* base = in + (size_t)bc * 513 * 1024 + tbase;
        for (int idx = tid; idx < 257 * 8; idx += 256) {
            int f = idx >> 3, j = idx & 7;
            float2 X = base[(size_t)f * 1024 + j];
            float2 Y = base[(size_t)(512 - f) * 1024 + j];
            if (f == 0) { X.y = 0.f; Y.y = 0.f; }    // c2r: Im(X[0]), Im(X[512]) ignored
            float2 w = tw1024[f];
            float2 A = make_float2(X.x + Y.x, X.y - Y.y);   // X[f] + conj(X[512-f])
            float2 D = make_float2(X.x - Y.x, X.y + Y.y);   // X[f] - conj(X[512-f])
            float2 wD = cmul(w, D);
            buf[j * BUFS + f] = make_float2((A.x - wD.y) * SC, (A.y + wD.x) * SC);
            if (f > 0 && f < 256)
                buf[j * BUFS + (512 - f)] = make_float2((A.x + wD.y) * SC, (-A.y + wD.x) * SC);
        }
    }
    __syncthreads();

    // ================= warp-local 512-pt inverse FFT (f = f0 + 16 f1 + 256 f2) ==========
    const int h = l >> 4;        // phase-A half / later m2
    const int f0 = l & 15;
    const float2 R16 = make_float2(0.92387953251128675f, 0.38268343236508977f); // e^{2pi i/16}
    const float2 RQ  = make_float2(0.98078528040323044f, 0.19509032201612827f); // e^{2pi i/32}

    // Phase A: radix-2 over f2 with twiddle e^{2 pi i m2 f1/32}; f1 = h + 2v
    float2 U0[8], U1[8];
    {
        float2 wA = h ? RQ : make_float2(1.f, 0.f);
        #pragma unroll
        for (int v = 0; v < 8; v++) {
            float2 x = buf[jf * BUFS + l + 32 * v];
            float2 y = buf[jf * BUFS + l + 32 * v + 256];
            U0[v] = cadd(x, y);
            U1[v] = cmul(csub(x, y), wA);
            wA = cmul(wA, R16);
        }
    }

    // A->B exchange (pairs l <-> l^16): lane 16*m2+f0 gathers all 16 f1
    float2 W[16];
    #pragma unroll
    for (int v = 0; v < 8; v++) {
        float2 send = h ? U0[v] : U1[v];
        float2 got;
        got.x = __shfl_xor_sync(0xffffffffu, send.x, 16);
        got.y = __shfl_xor_sync(0xffffffffu, send.y, 16);
        W[2 * v]     = h ? got   : U0[v];
        W[2 * v + 1] = h ? U1[v] : got;
    }

    // Phase B: radix-16 over f1, then twiddle e^{2 pi i (m2 + 2 m1) f0 / 512}
    float2 V[16];
    bfly16(W, V);
    {
        float2 w = tw1024[2 * h * f0];      // e^{2 pi i m2 f0/512}
        float2 rho = tw1024[4 * f0];        // e^{2 pi i 2 f0/512}
        #pragma unroll
        for (int m1 = 0; m1 < 16; m1++) { V[m1] = cmul(V[m1], w); w = cmul(w, rho); }
    }

    // B->C: 16x16 register transpose within each 16-lane half (lane f0 <-> slot m1)
    #pragma unroll
    for (int mask = 1; mask <= 8; mask <<= 1) {
        bool up = (l & mask) != 0;
        #pragma unroll
        for (int s0 = 0; s0 < 16; s0++) {
            if ((s0 & mask) == 0) {
                int s1 = s0 | mask;
                float2 lo = V[s0], hi = V[s1];
                float2 send = up ? lo : hi;
                float2 got;
                got.x = __shfl_xor_sync(0xffffffffu, send.x, mask);
                got.y = __shfl_xor_sync(0xffffffffu, send.y, mask);
                if (up) V[s0] = got; else V[s1] = got;
            }
        }
    }

    // Phase C: radix-16 over f0 -> z[m2 + 2 m1 + 32 m0] in slot m0
    float2 Z[16];
    bfly16(V, Z);

    // ---- Hann window: x[2m]=Re z * h(2m), x[2m+1]=Im z * h(2m+1); m = q + 32 m0 ----
    const int q = h + 2 * f0;    // bijection of lane
    {
        float2 e = tw1024[2 * q];        // e^{2 pi i m/512} at m0=0
        float2 o = tw1024[2 * q + 1];    // e^{2 pi i (2m+1)/1024} at m0=0
        #pragma unroll
        for (int m0 = 0; m0 < 16; m0++) {
            Z[m0].x *= (0.5f - 0.5f * e.x);
            Z[m0].y *= (0.5f - 0.5f * o.x);
            e = cmul(e, R16);
            o = cmul(o, R16);
        }
    }

    // ---- OLA: 4 rounds, chunk c=(r+2jf)&3 (Latin: regions jf+c distinct per round).
    //      Round 0 touch is every region's first -> plain store for interior regions. ----
    const int accbase = 128 * jf + q;
#define OLA4(C)                                                                      \
    {                                                                                \
        float2* p = &acc2[accbase + ((C) << 7)];                                     \
        if (store) { p[0] = Z[4*(C)]; p[32] = Z[4*(C)+1]; p[64] = Z[4*(C)+2]; p[96] = Z[4*(C)+3]; } \
        else { p[0] = cadd(p[0], Z[4*(C)]); p[32] = cadd(p[32], Z[4*(C)+1]);          \
               p[64] = cadd(p[64], Z[4*(C)+2]); p[96] = cadd(p[96], Z[4*(C)+3]); }    \
    }
    #pragma unroll
    for (int r = 0; r < 4; r++) {
        int c = (r + 2 * jf) & 3;
        int region = jf + c;
        bool store = (r == 0) && (region >= 3) && (region < 8);
        if (c == 0) OLA4(0)
        else if (c == 1) OLA4(1)
        else if (c == 2) OLA4(2)
        else OLA4(3)
        __syncthreads();
    }
#undef OLA4

    // ---- writeout: interior exclusively owned -> store; edges -> atomicAdd ----
    const float* accf = (const float*)acc2;
    float* obase = out + (size_t)bc * OUT_PER_BC;
    const int q0 = tbase << 8;   // 256 * tbase
    for (int idx = tid; idx < ACC_FLOATS; idx += 256) {
        int qq = q0 + idx;
        if (qq < 512) continue;              // crop y[:, :512]
        float v = accf[idx];
        int p = qq - 512;
        if (idx >= INT_LO_F && idx < INT_HI_F) obase[p] = v;
        else atomicAdd(&obase[p], v);
    }
}

extern "C" void kernel_launch(void* const* d_in, const int* in_sizes, int n_in,
                              void* d_out, int out_size) {
    const float2* in = (const float2*)d_in[0];
    float* out = (float*)d_out;
    // zero output (edge atomics require it; interior is overwritten by plain stores)
    cudaMemsetAsync(d_out, 0, (size_t)out_size * sizeof(float), 0);
    dim3 grid(1024 / FPC, 64);   // (t-groups, bc)
    istft_kernel<<<grid, 256>>>(in, out);
}